// round 16
// baseline (speedup 1.0000x reference)
#include <cuda_runtime.h>
#include <cstdint>
#include <cstddef>

// Problem constants
#define BB 32
#define TT 2048
#define DD 256
#define HH 512
#define G4 2048           // 4*H
#define KTOT 768          // H + D

#define NCTA 128
#define NTHR 512

// ---- shared memory layout (float offsets) ----
#define OFF_WS  0                          // Ws[768][32] dup-pairs   96 KB
#define OFF_HX  (KTOT * 32)                // hx[768][36]             108 KB
                                           // red[32][258] float2 ALIASES hx h-rows
#define OFF_GB  (OFF_HX + KTOT * 36)       // gb2: 2*256 float2 = 1024 floats
#define OFF_BS  (OFF_GB + 1024)            // bias[16]
#define OFF_CST (OFF_BS + 16)              // c state [b*4+u]
#define OFF_LC  (OFF_CST + 128)            // latched c
#define OFF_LH  (OFF_LC + 128)             // latched h
#define OFF_LEN (OFF_LH + 128)             // datalens[32] (int)
#define SMEM_FLOATS (OFF_LEN + 32)
#define SMEM_BYTES  (SMEM_FLOATS * 4)      // ~210 KB

// Persistent cross-CTA state (monotone across replays; NEVER reset).
// Invariants: g_cnt == 0 (mod NCTA) at every run start (each complete run adds
// NCTA*TT); g_flag advances only after all NCTA CTAs of the current run arrive.
__device__ __align__(16) float g_hT[2][HH * BB];  // double-buffered h, layout [k][b]
__device__ unsigned int g_cnt;                     // arrival counter (RMW line)
__device__ __align__(128) unsigned int g_flag;     // step flag (poll line, separate)

// ---- packed f32x2 + sync helpers (sm_103a) ----
#define FMA2(acc, h2, w2) \
    asm("fma.rn.f32x2 %0, %1, %2, %0;" : "+l"(acc) : "l"(h2), "l"(w2))
#define ADD2(acc, v) \
    asm("add.rn.f32x2 %0, %0, %1;" : "+l"(acc) : "l"(v))

__device__ __forceinline__ unsigned int ldacq(const unsigned int* p) {
    unsigned int v;
    asm volatile("ld.acquire.gpu.global.u32 %0, [%1];" : "=r"(v) : "l"(p));
    return v;
}
__device__ __forceinline__ unsigned int atom_add_acqrel(unsigned int* p, unsigned int v) {
    unsigned int old;
    asm volatile("atom.add.acq_rel.gpu.global.u32 %0, [%1], %2;"
                 : "=r"(old) : "l"(p), "r"(v) : "memory");
    return old;
}
__device__ __forceinline__ void st_release(unsigned int* p, unsigned int v) {
    asm volatile("st.release.gpu.global.u32 [%0], %1;" :: "l"(p), "r"(v) : "memory");
}

__device__ __forceinline__ float sigf(float x) {
    return __fdividef(1.0f, 1.0f + __expf(-x));
}
__device__ __forceinline__ float tanhfast(float x) {
    return 1.0f - __fdividef(2.0f, __expf(2.0f * x) + 1.0f);
}

// One K-step: 4 batch-pairs (8 batches) x 4 cols; weights pre-duplicated.
#define K_STEP(WP, HP)                                                        \
    {                                                                         \
        ulonglong2 hA = *(const ulonglong2*)(HP);                             \
        ulonglong2 hB = *(const ulonglong2*)((HP) + 4);                       \
        ulonglong2 wA = *(const ulonglong2*)(WP);                             \
        ulonglong2 wB = *(const ulonglong2*)((WP) + 4);                       \
        FMA2(a00, hA.x, wA.x); FMA2(a01, hA.x, wA.y);                         \
        FMA2(a02, hA.x, wB.x); FMA2(a03, hA.x, wB.y);                         \
        FMA2(a10, hA.y, wA.x); FMA2(a11, hA.y, wA.y);                         \
        FMA2(a12, hA.y, wB.x); FMA2(a13, hA.y, wB.y);                         \
        FMA2(a20, hB.x, wA.x); FMA2(a21, hB.x, wA.y);                         \
        FMA2(a22, hB.x, wB.x); FMA2(a23, hB.x, wB.y);                         \
        FMA2(a30, hB.y, wA.x); FMA2(a31, hB.y, wA.y);                         \
        FMA2(a32, hB.y, wB.x); FMA2(a33, hB.y, wB.y);                         \
    }

__global__ void __launch_bounds__(NTHR, 1)
k_lstm(const float* __restrict__ X,     // [B][T][D]
       const int*   __restrict__ lens,  // [B]
       const float* __restrict__ Wi,    // [D][4H]
       const float* __restrict__ Wh,    // [H][4H]
       const float* __restrict__ bias,  // [4H]
       float* __restrict__ out)         // lc[B,H] | lh[B,H] | ys[B,T,H]
{
    extern __shared__ float sm[];
    float*  Ws   = sm + OFF_WS;             // [768][32] duplicated pairs
    float*  hx   = sm + OFF_HX;             // [768][36]
    float2* red  = (float2*)(sm + OFF_HX);  // [32][258], aliases hx h-rows
    float2* gb2  = (float2*)(sm + OFF_GB);  // [2][256]
    float*  bs   = sm + OFF_BS;
    float*  cst  = sm + OFF_CST;
    float*  lcs  = sm + OFF_LC;
    float*  lhs  = sm + OFF_LH;
    int*    slen = (int*)(sm + OFF_LEN);

    const int tid = threadIdx.x;
    const int hc  = blockIdx.x * 4;         // this CTA's 4 h-units

    // ---- per-run flag baseline ----
    // Safe: g_flag can only advance after ALL CTAs arrive once, and every CTA
    // reads fbase before its own first arrival -> read precedes first advance.
    unsigned int fbase = 0;
    if (tid == 0) fbase = *(volatile unsigned int*)&g_flag;

    // ---- one-time setup: stage duplicated weight slice ----
    for (int i = tid; i < KTOT * 4; i += NTHR) {
        int k = i >> 2, q = i & 3;
        const float* src = (k < HH) ? (Wh + (size_t)k * G4)
                                    : (Wi + (size_t)(k - HH) * G4);
        float4 w = *(const float4*)&src[q * HH + hc];
        float4* dst = (float4*)&Ws[k * 32 + q * 8];
        dst[0] = make_float4(w.x, w.x, w.y, w.y);
        dst[1] = make_float4(w.z, w.z, w.w, w.w);
    }
    if (tid < 16) bs[tid] = bias[(tid >> 2) * HH + hc + (tid & 3)];
    if (tid < BB) slen[tid] = lens[tid];
    if (tid < 128) { cst[tid] = 0.0f; lcs[tid] = 0.0f; lhs[tid] = 0.0f; }
    __syncthreads();

    // GEMM decomposition: 16 output tiles x 32-way K-split
    const int og = tid & 15;
    const int kg = tid >> 4;          // 0..31
    const int bg = og >> 2;           // batch-pair group (8 batches)
    const int cg = og & 3;            // col group (4 cols = one gate's 4 units)

    // x prefetch mapping: lane = batch (conflict-free STS), 16 d's per thread
    const int xb  = tid & 31;
    const int xdq = (tid >> 5) * 16;
    const float* xrow = X + (size_t)xb * TT * DD + xdq;

    float4 pf0, pf1, pf2, pf3;
    {
        pf0 = __ldcg((const float4*)(xrow +  0));
        pf1 = __ldcg((const float4*)(xrow +  4));
        pf2 = __ldcg((const float4*)(xrow +  8));
        pf3 = __ldcg((const float4*)(xrow + 12));
    }

    for (int s = 0; s < TT; s++) {
        // ---- store prefetched x(s): conflict-free ----
        {
            float* d0 = &hx[(HH + xdq) * 36 + xb];
            d0[0*36] = pf0.x; d0[1*36] = pf0.y; d0[ 2*36] = pf0.z; d0[ 3*36] = pf0.w;
            d0[4*36] = pf1.x; d0[5*36] = pf1.y; d0[ 6*36] = pf1.z; d0[ 7*36] = pf1.w;
            d0[8*36] = pf2.x; d0[9*36] = pf2.y; d0[10*36] = pf2.z; d0[11*36] = pf2.w;
            d0[12*36]= pf3.x; d0[13*36]= pf3.y; d0[14*36] = pf3.z; d0[15*36] = pf3.w;
        }
        __syncthreads();

        unsigned long long a00=0,a01=0,a02=0,a03=0, a10=0,a11=0,a12=0,a13=0,
                           a20=0,a21=0,a22=0,a23=0, a30=0,a31=0,a32=0,a33=0;

        // ---- x partial GEMM (h-independent: overlaps the barrier wait) ----
        {
            const float* wp = Ws + (HH + kg * 8) * 32 + cg * 8;
            const float* hp = hx + (HH + kg * 8) * 36 + bg * 8;
#pragma unroll
            for (int kk = 0; kk < 8; kk++) { K_STEP(wp, hp); wp += 32; hp += 36; }
        }

        // ---- prefetch x(s+1) ----
        if (s + 1 < TT) {
            const float* xr = xrow + (size_t)(s + 1) * DD;
            pf0 = __ldcg((const float4*)(xr +  0));
            pf1 = __ldcg((const float4*)(xr +  4));
            pf2 = __ldcg((const float4*)(xr +  8));
            pf3 = __ldcg((const float4*)(xr + 12));
        }

        if (s > 0) {
            // ---- grid barrier: poll read-only flag line, wrap-safe compare ----
            if (tid == 0) {
                unsigned int target = fbase + (unsigned int)s;
                while ((int)(ldacq(&g_flag) - target) < 0) __nanosleep(20);
            }
            __syncthreads();

            // ---- stage h(s-1) (L2-direct) ----
            {
                const float* src = g_hT[s & 1];
                for (int i = tid; i < (HH * BB) / 4; i += NTHR) {
                    int k = i >> 3, b4 = (i & 7) << 2;
                    float4 v = __ldcg((const float4*)&src[k * BB + b4]);
                    *(float4*)&hx[k * 36 + b4] = v;
                }
            }
            __syncthreads();

            // ---- h GEMM ----
            {
                const float* wp = Ws + (kg * 16) * 32 + cg * 8;
                const float* hp = hx + (kg * 16) * 36 + bg * 8;
#pragma unroll
                for (int kk = 0; kk < 16; kk++) { K_STEP(wp, hp); wp += 32; hp += 36; }
            }
        }
        __syncthreads();   // hx h-row reads done before red (aliased) overwrites

        // ---- K-split partial store: red[kg][pair*16 + col] ----
        {
            int base2 = kg * 258 + (bg * 4) * 16 + cg * 4;   // float2 units, 16B aligned
            *(ulonglong2*)&red[base2         ] = make_ulonglong2(a00, a01);
            *(ulonglong2*)&red[base2      + 2] = make_ulonglong2(a02, a03);
            *(ulonglong2*)&red[base2 + 16    ] = make_ulonglong2(a10, a11);
            *(ulonglong2*)&red[base2 + 16 + 2] = make_ulonglong2(a12, a13);
            *(ulonglong2*)&red[base2 + 32    ] = make_ulonglong2(a20, a21);
            *(ulonglong2*)&red[base2 + 32 + 2] = make_ulonglong2(a22, a23);
            *(ulonglong2*)&red[base2 + 48    ] = make_ulonglong2(a30, a31);
            *(ulonglong2*)&red[base2 + 48 + 2] = make_ulonglong2(a32, a33);
        }
        __syncthreads();

        // ---- reduction over kg: all 512 threads, f32x2 adds ----
        {
            int slot = tid & 255, half = tid >> 8;
            unsigned long long acc = 0ull;   // (+0.f, +0.f)
#pragma unroll
            for (int g = 0; g < 16; g++) {
                unsigned long long v =
                    *(const unsigned long long*)&red[(half * 16 + g) * 258 + slot];
                ADD2(acc, v);
            }
            *(unsigned long long*)&gb2[half * 256 + slot] = acc;
        }
        __syncthreads();

        // ---- gates / state update / publish ----
        if (tid < 128) {
            int b  = tid >> 2, u = tid & 3;
            int bp = b >> 1, hi = b & 1;
            int s0 = bp * 16 + u;
            float2 vi0 = gb2[s0     ], vi1 = gb2[256 + s0     ];
            float2 vf0 = gb2[s0 +  4], vf1 = gb2[256 + s0 +  4];
            float2 vg0 = gb2[s0 +  8], vg1 = gb2[256 + s0 +  8];
            float2 vo0 = gb2[s0 + 12], vo1 = gb2[256 + s0 + 12];
            float gi = (hi ? vi0.y + vi1.y : vi0.x + vi1.x) + bs[     u];
            float gf = (hi ? vf0.y + vf1.y : vf0.x + vf1.x) + bs[ 4 + u];
            float gg = (hi ? vg0.y + vg1.y : vg0.x + vg1.x) + bs[ 8 + u];
            float go = (hi ? vo0.y + vo1.y : vo0.x + vo1.x) + bs[12 + u];

            float c_old = cst[tid];
            float cn = sigf(gf) * c_old + sigf(gi) * tanhfast(gg);
            float hn = sigf(go) * tanhfast(cn);
            cst[tid] = cn;

            // publish h(s) to the buffer step s+1 reads
            g_hT[(s + 1) & 1][(hc + u) * BB + b] = hn;

            // ys output
            out[2 * BB * HH + ((size_t)b * TT + s) * HH + hc + u] = hn;

            if (s < slen[b]) { lcs[tid] = cn; lhs[tid] = hn; }
        }
        __syncthreads();   // publishes ordered before the arrival RMW

        // ---- arrive: acq_rel RMW; the NCTA-th arriver of this step releases
        //      the flag. g_cnt % NCTA == 0 at run start (invariant), so
        //      old % NCTA == NCTA-1 identifies the last arriver, baseline-free.
        if (tid == 0) {
            unsigned int old = atom_add_acqrel(&g_cnt, 1u);
            if ((old & (NCTA - 1)) == NCTA - 1)
                st_release(&g_flag, fbase + (unsigned int)(s + 1));
        }
    }

    // ---- final latched carry ----
    if (tid < 128) {
        int b = tid >> 2, u = tid & 3;
        out[          (size_t)b * HH + hc + u] = lcs[tid];   // lc
        out[BB * HH + (size_t)b * HH + hc + u] = lhs[tid];   // lh
    }
}

extern "C" void kernel_launch(void* const* d_in, const int* in_sizes, int n_in,
                              void* d_out, int out_size) {
    const float* X    = (const float*)d_in[0];   // datamat [B,T,D]
    const int*   lens = (const int*)  d_in[1];   // datalens [B]
    const float* Wi   = (const float*)d_in[2];   // [D,4H]
    const float* Wh   = (const float*)d_in[3];   // [H,4H]
    const float* bias = (const float*)d_in[4];   // [4H]
    float* out = (float*)d_out;

    cudaFuncSetAttribute(k_lstm, cudaFuncAttributeMaxDynamicSharedMemorySize,
                         SMEM_BYTES);

    k_lstm<<<NCTA, NTHR, SMEM_BYTES>>>(X, lens, Wi, Wh, bias, out);
}

// round 17
// speedup vs baseline: 1.1001x; 1.1001x over previous
#include <cuda_runtime.h>
#include <cstdint>
#include <cstddef>

// Problem constants
#define BB 32
#define TT 2048
#define DD 256
#define HH 512
#define G4 2048           // 4*H
#define KTOT 768          // H + D

#define NCTA 128
#define NTHR 512

// ---- shared memory layout (float offsets) ----
#define OFF_WS  0                          // Ws[768][16]            48 KB
#define OFF_HX  (KTOT * 16)                // hx[768][36]            108 KB
                                           // red[32][258] float2 ALIASES hx h-rows
#define OFF_GB  (OFF_HX + KTOT * 36)       // gb2: 2*256 float2 = 1024 floats
#define OFF_BS  (OFF_GB + 1024)            // bias[16]
#define OFF_CST (OFF_BS + 16)              // c state [b*4+u]
#define OFF_LC  (OFF_CST + 128)            // latched c
#define OFF_LH  (OFF_LC + 128)             // latched h
#define OFF_LEN (OFF_LH + 128)             // datalens[32] (int)
#define SMEM_FLOATS (OFF_LEN + 32)
#define SMEM_BYTES  (SMEM_FLOATS * 4)      // ~162 KB

// Persistent cross-CTA state (monotone across replays; NEVER reset).
// Invariants: g_cnt == 0 (mod NCTA) at every run start (each complete run adds
// NCTA*TT); g_flag advances only after all NCTA CTAs of the current run arrive.
__device__ __align__(16) float g_hT[2][HH * BB];  // double-buffered h, layout [k][b]
__device__ unsigned int g_cnt;                     // arrival counter (RMW line)
__device__ __align__(128) unsigned int g_flag;     // step flag (poll line, separate)

// ---- packed f32x2 + sync helpers (sm_103a) ----
__device__ __forceinline__ unsigned long long dup2(float f) {
    unsigned long long r;
    asm("mov.b64 %0, {%1, %1};" : "=l"(r) : "r"(__float_as_uint(f)));
    return r;
}
#define FMA2(acc, h2, w2) \
    asm("fma.rn.f32x2 %0, %1, %2, %0;" : "+l"(acc) : "l"(h2), "l"(w2))
#define ADD2(acc, v) \
    asm("add.rn.f32x2 %0, %0, %1;" : "+l"(acc) : "l"(v))

__device__ __forceinline__ unsigned int ldacq(const unsigned int* p) {
    unsigned int v;
    asm volatile("ld.acquire.gpu.global.u32 %0, [%1];" : "=r"(v) : "l"(p));
    return v;
}
__device__ __forceinline__ unsigned int atom_add_acqrel(unsigned int* p, unsigned int v) {
    unsigned int old;
    asm volatile("atom.add.acq_rel.gpu.global.u32 %0, [%1], %2;"
                 : "=r"(old) : "l"(p), "r"(v) : "memory");
    return old;
}
__device__ __forceinline__ void st_release(unsigned int* p, unsigned int v) {
    asm volatile("st.release.gpu.global.u32 [%0], %1;" :: "l"(p), "r"(v) : "memory");
}

__device__ __forceinline__ float sigf(float x) {
    return __fdividef(1.0f, 1.0f + __expf(-x));
}
__device__ __forceinline__ float tanhfast(float x) {
    return 1.0f - __fdividef(2.0f, __expf(2.0f * x) + 1.0f);
}

// One K-step: 4 batch-pairs (8 batches) x 4 cols, all operands in SMEM.
// (R13 version: single float4 weight load + dup MOVs — 48B LDS per 32 MACs.)
#define K_STEP(WP, HP)                                                        \
    {                                                                         \
        ulonglong2 hA = *(const ulonglong2*)(HP);                             \
        ulonglong2 hB = *(const ulonglong2*)((HP) + 4);                       \
        float4 wv = *(const float4*)(WP);                                     \
        unsigned long long w0 = dup2(wv.x), w1 = dup2(wv.y),                  \
                           w2 = dup2(wv.z), w3 = dup2(wv.w);                  \
        FMA2(a00, hA.x, w0); FMA2(a01, hA.x, w1);                             \
        FMA2(a02, hA.x, w2); FMA2(a03, hA.x, w3);                             \
        FMA2(a10, hA.y, w0); FMA2(a11, hA.y, w1);                             \
        FMA2(a12, hA.y, w2); FMA2(a13, hA.y, w3);                             \
        FMA2(a20, hB.x, w0); FMA2(a21, hB.x, w1);                             \
        FMA2(a22, hB.x, w2); FMA2(a23, hB.x, w3);                             \
        FMA2(a30, hB.y, w0); FMA2(a31, hB.y, w1);                             \
        FMA2(a32, hB.y, w2); FMA2(a33, hB.y, w3);                             \
    }

__global__ void __launch_bounds__(NTHR, 1)
k_lstm(const float* __restrict__ X,     // [B][T][D]
       const int*   __restrict__ lens,  // [B]
       const float* __restrict__ Wi,    // [D][4H]
       const float* __restrict__ Wh,    // [H][4H]
       const float* __restrict__ bias,  // [4H]
       float* __restrict__ out)         // lc[B,H] | lh[B,H] | ys[B,T,H]
{
    extern __shared__ float sm[];
    float*  Ws   = sm + OFF_WS;             // [768][16]
    float*  hx   = sm + OFF_HX;             // [768][36]
    float2* red  = (float2*)(sm + OFF_HX);  // [32][258], aliases hx h-rows
    float2* gb2  = (float2*)(sm + OFF_GB);  // [2][256]
    float*  bs   = sm + OFF_BS;
    float*  cst  = sm + OFF_CST;
    float*  lcs  = sm + OFF_LC;
    float*  lhs  = sm + OFF_LH;
    int*    slen = (int*)(sm + OFF_LEN);

    const int tid = threadIdx.x;
    const int hc  = blockIdx.x * 4;         // this CTA's 4 h-units

    // ---- per-run flag baseline ----
    // Safe: g_flag can only advance after ALL CTAs arrive once, and every CTA
    // reads fbase before its own first arrival -> read precedes first advance.
    unsigned int fbase = 0;
    if (tid == 0) fbase = *(volatile unsigned int*)&g_flag;

    // ---- one-time setup: stage weight slice ----
    for (int i = tid; i < KTOT * 4; i += NTHR) {
        int k = i >> 2, q = i & 3;
        const float* src = (k < HH) ? (Wh + (size_t)k * G4)
                                    : (Wi + (size_t)(k - HH) * G4);
        *(float4*)&Ws[k * 16 + q * 4] = *(const float4*)&src[q * HH + hc];
    }
    if (tid < 16) bs[tid] = bias[(tid >> 2) * HH + hc + (tid & 3)];
    if (tid < BB) slen[tid] = lens[tid];
    if (tid < 128) { cst[tid] = 0.0f; lcs[tid] = 0.0f; lhs[tid] = 0.0f; }
    __syncthreads();

    // GEMM decomposition: 16 output tiles x 32-way K-split
    const int og = tid & 15;
    const int kg = tid >> 4;          // 0..31
    const int bg = og >> 2;           // batch-pair group (8 batches)
    const int cg = og & 3;            // col group (4 cols)

    // x prefetch mapping: lane = batch (conflict-free STS), 16 d's per thread
    const int xb  = tid & 31;
    const int xdq = (tid >> 5) * 16;
    const float* xrow = X + (size_t)xb * TT * DD + xdq;

    float4 pf0, pf1, pf2, pf3;
    {
        pf0 = __ldcg((const float4*)(xrow +  0));
        pf1 = __ldcg((const float4*)(xrow +  4));
        pf2 = __ldcg((const float4*)(xrow +  8));
        pf3 = __ldcg((const float4*)(xrow + 12));
    }

    for (int s = 0; s < TT; s++) {
        // ---- store prefetched x(s): conflict-free ----
        {
            float* d0 = &hx[(HH + xdq) * 36 + xb];
            d0[0*36] = pf0.x; d0[1*36] = pf0.y; d0[ 2*36] = pf0.z; d0[ 3*36] = pf0.w;
            d0[4*36] = pf1.x; d0[5*36] = pf1.y; d0[ 6*36] = pf1.z; d0[ 7*36] = pf1.w;
            d0[8*36] = pf2.x; d0[9*36] = pf2.y; d0[10*36] = pf2.z; d0[11*36] = pf2.w;
            d0[12*36]= pf3.x; d0[13*36]= pf3.y; d0[14*36] = pf3.z; d0[15*36] = pf3.w;
        }
        __syncthreads();

        unsigned long long a00=0,a01=0,a02=0,a03=0, a10=0,a11=0,a12=0,a13=0,
                           a20=0,a21=0,a22=0,a23=0, a30=0,a31=0,a32=0,a33=0;

        // ---- x partial GEMM (h-independent: overlaps the barrier wait) ----
        {
            const float* wp = Ws + (HH + kg * 8) * 16 + cg * 4;
            const float* hp = hx + (HH + kg * 8) * 36 + bg * 8;
#pragma unroll
            for (int kk = 0; kk < 8; kk++) { K_STEP(wp, hp); wp += 16; hp += 36; }
        }

        // ---- prefetch x(s+1) ----
        if (s + 1 < TT) {
            const float* xr = xrow + (size_t)(s + 1) * DD;
            pf0 = __ldcg((const float4*)(xr +  0));
            pf1 = __ldcg((const float4*)(xr +  4));
            pf2 = __ldcg((const float4*)(xr +  8));
            pf3 = __ldcg((const float4*)(xr + 12));
        }

        if (s > 0) {
            // ---- grid barrier: full-rate poll on read-only flag line ----
            if (tid == 0) {
                unsigned int target = fbase + (unsigned int)s;
                while ((int)(ldacq(&g_flag) - target) < 0) { }
            }
            __syncthreads();

            // ---- stage h(s-1) (L2-direct, all 8 LDGs in flight) ----
            {
                const float* src = g_hT[s & 1];
#pragma unroll
                for (int r = 0; r < 8; r++) {
                    int i = tid + r * NTHR;
                    int k = i >> 3, b4 = (i & 7) << 2;
                    float4 v = __ldcg((const float4*)&src[k * BB + b4]);
                    *(float4*)&hx[k * 36 + b4] = v;
                }
            }
            __syncthreads();

            // ---- h GEMM ----
            {
                const float* wp = Ws + (kg * 16) * 16 + cg * 4;
                const float* hp = hx + (kg * 16) * 36 + bg * 8;
#pragma unroll
                for (int kk = 0; kk < 16; kk++) { K_STEP(wp, hp); wp += 16; hp += 36; }
            }
        }
        __syncthreads();   // hx h-row reads done before red (aliased) overwrites

        // ---- K-split partial store: red[kg][pair*16 + col] ----
        {
            int base2 = kg * 258 + (bg * 4) * 16 + cg * 4;   // float2 units, 16B aligned
            *(ulonglong2*)&red[base2         ] = make_ulonglong2(a00, a01);
            *(ulonglong2*)&red[base2      + 2] = make_ulonglong2(a02, a03);
            *(ulonglong2*)&red[base2 + 16    ] = make_ulonglong2(a10, a11);
            *(ulonglong2*)&red[base2 + 16 + 2] = make_ulonglong2(a12, a13);
            *(ulonglong2*)&red[base2 + 32    ] = make_ulonglong2(a20, a21);
            *(ulonglong2*)&red[base2 + 32 + 2] = make_ulonglong2(a22, a23);
            *(ulonglong2*)&red[base2 + 48    ] = make_ulonglong2(a30, a31);
            *(ulonglong2*)&red[base2 + 48 + 2] = make_ulonglong2(a32, a33);
        }
        __syncthreads();

        // ---- reduction over kg: all 512 threads, f32x2 adds ----
        {
            int slot = tid & 255, half = tid >> 8;
            unsigned long long acc = 0ull;   // (+0.f, +0.f)
#pragma unroll
            for (int g = 0; g < 16; g++) {
                unsigned long long v =
                    *(const unsigned long long*)&red[(half * 16 + g) * 258 + slot];
                ADD2(acc, v);
            }
            *(unsigned long long*)&gb2[half * 256 + slot] = acc;
        }
        __syncthreads();

        // ---- gates / state update / publish ----
        if (tid < 128) {
            int b  = tid >> 2, u = tid & 3;
            int bp = b >> 1, hi = b & 1;
            int s0 = bp * 16 + u;
            float2 vi0 = gb2[s0     ], vi1 = gb2[256 + s0     ];
            float2 vf0 = gb2[s0 +  4], vf1 = gb2[256 + s0 +  4];
            float2 vg0 = gb2[s0 +  8], vg1 = gb2[256 + s0 +  8];
            float2 vo0 = gb2[s0 + 12], vo1 = gb2[256 + s0 + 12];
            float gi = (hi ? vi0.y + vi1.y : vi0.x + vi1.x) + bs[     u];
            float gf = (hi ? vf0.y + vf1.y : vf0.x + vf1.x) + bs[ 4 + u];
            float gg = (hi ? vg0.y + vg1.y : vg0.x + vg1.x) + bs[ 8 + u];
            float go = (hi ? vo0.y + vo1.y : vo0.x + vo1.x) + bs[12 + u];

            float c_old = cst[tid];
            float cn = sigf(gf) * c_old + sigf(gi) * tanhfast(gg);
            float hn = sigf(go) * tanhfast(cn);
            cst[tid] = cn;

            // publish h(s) to the buffer step s+1 reads
            g_hT[(s + 1) & 1][(hc + u) * BB + b] = hn;

            // ys output
            out[2 * BB * HH + ((size_t)b * TT + s) * HH + hc + u] = hn;

            if (s < slen[b]) { lcs[tid] = cn; lhs[tid] = hn; }
        }
        __syncthreads();   // publishes ordered before the arrival RMW

        // ---- arrive: acq_rel RMW; last arriver of this step releases the flag.
        //      g_cnt % NCTA == 0 at run start, so old % NCTA == NCTA-1 is the
        //      last arriver — baseline-free, no reset needed.
        if (tid == 0) {
            unsigned int old = atom_add_acqrel(&g_cnt, 1u);
            if ((old & (NCTA - 1)) == NCTA - 1)
                st_release(&g_flag, fbase + (unsigned int)(s + 1));
        }
    }

    // ---- final latched carry ----
    if (tid < 128) {
        int b = tid >> 2, u = tid & 3;
        out[          (size_t)b * HH + hc + u] = lcs[tid];   // lc
        out[BB * HH + (size_t)b * HH + hc + u] = lhs[tid];   // lh
    }
}

extern "C" void kernel_launch(void* const* d_in, const int* in_sizes, int n_in,
                              void* d_out, int out_size) {
    const float* X    = (const float*)d_in[0];   // datamat [B,T,D]
    const int*   lens = (const int*)  d_in[1];   // datalens [B]
    const float* Wi   = (const float*)d_in[2];   // [D,4H]
    const float* Wh   = (const float*)d_in[3];   // [H,4H]
    const float* bias = (const float*)d_in[4];   // [4H]
    float* out = (float*)d_out;

    cudaFuncSetAttribute(k_lstm, cudaFuncAttributeMaxDynamicSharedMemorySize,
                         SMEM_BYTES);

    k_lstm<<<NCTA, NTHR, SMEM_BYTES>>>(X, lens, Wi, Wh, bias, out);
}